// round 3
// baseline (speedup 1.0000x reference)
#include <cuda_runtime.h>
#include <cstdint>

// Scatter-add message passing, sort-based (no fp32 atomics on the output):
//  1) detect idx dtype + zero histogram
//  2) histogram of dst
//  3) exclusive scan -> CSR offsets (+ cursor copy)
//  4) bin src ids by dst (counting-sort scatter)
//  5) per-dst segmented reduce: 16 lanes/node, float4 chunk each, register
//     accumulation, single coalesced 256B store per node.
//
// Removes the 204.8 MB atomic-scatter L2 traffic of the R2 kernel.

#define MAX_E 800000
#define MAX_N 50000

__device__ int g_idx_is64;
__device__ int d_counts[MAX_N];
__device__ int d_cursor[MAX_N];
__device__ int d_offsets[MAX_N + 1];
__device__ int d_src_sorted[MAX_E];

__device__ __forceinline__ int load_idx(const void* ei_raw, int pos) {
    if (g_idx_is64) return (int)__ldg((const long long*)ei_raw + pos);
    return __ldg((const int*)ei_raw + pos);
}

// Zero histogram; thread 0 also detects int32 vs int64 layout:
// values are nonneg < 50000, so int64 layout => hi words of first 64 entries
// are all zero; int32 layout => odd slots are uniform ids (P[all 0] ~ 0).
__global__ void k_init(const int* __restrict__ ei_raw, int N) {
    int i = blockIdx.x * blockDim.x + threadIdx.x;
    if (i < N) d_counts[i] = 0;
    if (i == 0) {
        int all_hi_zero = 1;
        for (int j = 0; j < 64; j++)
            if (ei_raw[2 * j + 1] != 0) { all_hi_zero = 0; break; }
        g_idx_is64 = all_hi_zero;
    }
}

__global__ void k_hist(const void* __restrict__ ei_raw, int E) {
    int e = blockIdx.x * blockDim.x + threadIdx.x;
    if (e >= E) return;
    atomicAdd(&d_counts[load_idx(ei_raw, e)], 1);
}

// Single-block exclusive scan over N counts -> offsets (+ cursor init).
__global__ void k_scan(int N, int E) {
    __shared__ int s[1024];
    int t = threadIdx.x;
    int chunk = (N + 1023) / 1024;
    int lo = t * chunk;
    int hi = min(lo + chunk, N);

    int sum = 0;
    for (int i = lo; i < hi; i++) sum += d_counts[i];
    s[t] = sum;
    __syncthreads();
    for (int off = 1; off < 1024; off <<= 1) {
        int v = (t >= off) ? s[t - off] : 0;
        __syncthreads();
        s[t] += v;
        __syncthreads();
    }
    int run = (t > 0) ? s[t - 1] : 0;   // exclusive base for this chunk
    for (int i = lo; i < hi; i++) {
        d_offsets[i] = run;
        d_cursor[i] = run;
        run += d_counts[i];
    }
    if (t == 0) d_offsets[N] = E;
}

__global__ void k_bin(const void* __restrict__ ei_raw, int E) {
    int e = blockIdx.x * blockDim.x + threadIdx.x;
    if (e >= E) return;
    int dst = load_idx(ei_raw, e);
    int src = load_idx(ei_raw, E + e);
    int pos = atomicAdd(&d_cursor[dst], 1);
    d_src_sorted[pos] = src;
}

// 16 lanes per node; lane c accumulates float4 chunk c over the node's edges.
__global__ void k_reduce(const float* __restrict__ x,
                         float* __restrict__ out, int N) {
    int tid = blockIdx.x * blockDim.x + threadIdx.x;
    int node = tid >> 4;
    int c = tid & 15;
    if (node >= N) return;

    int beg = __ldg(&d_offsets[node]);
    int end = __ldg(&d_offsets[node + 1]);

    float4 acc = make_float4(0.f, 0.f, 0.f, 0.f);
    #pragma unroll 2
    for (int i = beg; i < end; i++) {
        int src = __ldg(&d_src_sorted[i]);
        float4 v = __ldg((const float4*)(x + (size_t)src * 64) + c);
        acc.x += v.x; acc.y += v.y; acc.z += v.z; acc.w += v.w;
    }
    ((float4*)(out + (size_t)node * 64))[c] = acc;
}

extern "C" void kernel_launch(void* const* d_in, const int* in_sizes, int n_in,
                              void* d_out, int out_size) {
    const float* x = (const float*)d_in[0];
    const void* ei = d_in[1];
    float* out = (float*)d_out;

    int E = in_sizes[1] / 2;          // edge_index is [2, E]
    int N = out_size / 64;            // nodes

    int tb = 256;
    k_init<<<(N + tb - 1) / tb, tb>>>((const int*)ei, N);
    k_hist<<<(E + tb - 1) / tb, tb>>>(ei, E);
    k_scan<<<1, 1024>>>(N, E);
    k_bin<<<(E + tb - 1) / tb, tb>>>(ei, E);
    long long total = (long long)N * 16;
    k_reduce<<<(int)((total + tb - 1) / tb), tb>>>(x, out, N);
}

// round 4
// speedup vs baseline: 2.6178x; 2.6178x over previous
#include <cuda_runtime.h>
#include <cstdint>

// Scatter-add message passing: out[dst] += x[src]
// x: [N, 64] fp32; edge_index: [2, E], int32 or int64 (detected on-device).
//
// Mapping: 16 lanes per edge-GROUP of 4 consecutive edges; lane c owns float4
// chunk c. Phase-ordered: load all 8 indices (two broadcast int4s), then 4
// independent float4 gathers, then 4 v4 REDs. 4 independent memory chains per
// thread hide L2 latency (R2 was a single chain -> issue 24%, nothing
// saturated).

__device__ int g_idx_is64;

__global__ void detect_idx_kernel(const int* __restrict__ ei_raw) {
    int all_hi_zero = 1;
    #pragma unroll
    for (int i = 0; i < 64; i++) {
        if (ei_raw[2 * i + 1] != 0) { all_hi_zero = 0; break; }
    }
    g_idx_is64 = all_hi_zero;   // values < 50000 => int64 hi words all zero
}

__device__ __forceinline__ void red_v4(float* out, int dst, int c, float4 v) {
    float4* op = (float4*)(out + (size_t)dst * 64) + c;
    asm volatile("red.global.add.v4.f32 [%0], {%1, %2, %3, %4};"
                 :: "l"(op), "f"(v.x), "f"(v.y), "f"(v.z), "f"(v.w)
                 : "memory");
}

__global__ void mp_scatter4_kernel(const float* __restrict__ x,
                                   const void* __restrict__ ei_raw,
                                   float* __restrict__ out,
                                   int E, int G) {
    int tid = blockIdx.x * blockDim.x + threadIdx.x;
    int g = tid >> 4;           // group of 4 consecutive edges
    int c = tid & 15;           // float4 chunk within the 64-float row
    if (g >= G) return;

    int e0 = g << 2;
    int n = min(4, E - e0);     // edges in this group (tail-safe)

    int dst[4], src[4];
    if (g_idx_is64) {
        const long long* ei = (const long long*)ei_raw;
        #pragma unroll
        for (int k = 0; k < 4; k++) {
            int e = e0 + ((k < n) ? k : 0);
            dst[k] = (int)__ldg(ei + e);
            src[k] = (int)__ldg(ei + E + e);
        }
    } else {
        const int* ei = (const int*)ei_raw;
        if (n == 4) {           // aligned: e0 % 4 == 0
            int4 d4 = __ldg((const int4*)(ei + e0));
            int4 s4 = __ldg((const int4*)(ei + E + e0));
            dst[0] = d4.x; dst[1] = d4.y; dst[2] = d4.z; dst[3] = d4.w;
            src[0] = s4.x; src[1] = s4.y; src[2] = s4.z; src[3] = s4.w;
        } else {
            #pragma unroll
            for (int k = 0; k < 4; k++) {
                int e = e0 + ((k < n) ? k : 0);
                dst[k] = __ldg(ei + e);
                src[k] = __ldg(ei + E + e);
            }
        }
    }

    // Phase 2: all gathers issued before any RED (asm memory clobber would
    // otherwise serialize load->red->load->red).
    float4 v[4];
    #pragma unroll
    for (int k = 0; k < 4; k++)
        v[k] = __ldg((const float4*)(x + (size_t)src[k] * 64) + c);

    // Phase 3: fire-and-forget reductions.
    #pragma unroll
    for (int k = 0; k < 4; k++)
        if (k < n) red_v4(out, dst[k], c, v[k]);
}

extern "C" void kernel_launch(void* const* d_in, const int* in_sizes, int n_in,
                              void* d_out, int out_size) {
    const float* x = (const float*)d_in[0];
    const void* ei = d_in[1];
    float* out = (float*)d_out;

    int E = in_sizes[1] / 2;            // edge_index is [2, E]
    int G = (E + 3) / 4;                // groups of 4 edges

    detect_idx_kernel<<<1, 1>>>((const int*)ei);
    cudaMemsetAsync(d_out, 0, (size_t)out_size * sizeof(float), 0);

    long long total = (long long)G * 16;
    int threads = 256;
    int blocks = (int)((total + threads - 1) / threads);
    mp_scatter4_kernel<<<blocks, threads>>>(x, ei, out, E, G);
}